// round 1
// baseline (speedup 1.0000x reference)
#include <cuda_runtime.h>
#include <math.h>

#define T_TOK 4096   // B*S
#define D_DIM 1024
#define E_NUM 8
#define H_DIM 4096
#define CAP   4096   // worst-case tokens per expert

// ---- static scratch (allowed: __device__ globals) ----
__device__ float g_hbuf[(size_t)E_NUM * CAP * H_DIM];   // 512 MB
__device__ float g_ybuf[(size_t)E_NUM * CAP * D_DIM];   // 128 MB
__device__ int   g_counts[E_NUM];
__device__ int   g_list[E_NUM * CAP];
__device__ float g_gate[E_NUM * CAP];
__device__ int   g_pair[T_TOK * 2];

__global__ void zero_counts_kernel() {
    if (threadIdx.x < E_NUM) g_counts[threadIdx.x] = 0;
}

// ---------------- Router: one warp per token ----------------
__global__ void router_kernel(const float* __restrict__ x,
                              const float* __restrict__ noise,
                              const float* __restrict__ Wr, const float* __restrict__ br,
                              const float* __restrict__ Wn, const float* __restrict__ bn,
                              float* __restrict__ gate_out /* [T,E] */) {
    int warp = (blockIdx.x * blockDim.x + threadIdx.x) >> 5;
    int lane = threadIdx.x & 31;
    if (warp >= T_TOK) return;

    const float* xr = x + (size_t)warp * D_DIM;
    float aR[8], aN[8];
#pragma unroll
    for (int e = 0; e < 8; e++) { aR[e] = 0.f; aN[e] = 0.f; }

    for (int d0 = lane * 4; d0 < D_DIM; d0 += 32 * 4) {
        float4 xv = *(const float4*)(xr + d0);
        float xs[4] = {xv.x, xv.y, xv.z, xv.w};
#pragma unroll
        for (int u = 0; u < 4; ++u) {
            float xd = xs[u];
            const float4* wr = (const float4*)(Wr + (size_t)(d0 + u) * E_NUM);
            float4 r0 = wr[0], r1 = wr[1];
            const float4* wn = (const float4*)(Wn + (size_t)(d0 + u) * E_NUM);
            float4 q0 = wn[0], q1 = wn[1];
            aR[0] += xd * r0.x; aR[1] += xd * r0.y; aR[2] += xd * r0.z; aR[3] += xd * r0.w;
            aR[4] += xd * r1.x; aR[5] += xd * r1.y; aR[6] += xd * r1.z; aR[7] += xd * r1.w;
            aN[0] += xd * q0.x; aN[1] += xd * q0.y; aN[2] += xd * q0.z; aN[3] += xd * q0.w;
            aN[4] += xd * q1.x; aN[5] += xd * q1.y; aN[6] += xd * q1.z; aN[7] += xd * q1.w;
        }
    }
#pragma unroll
    for (int off = 16; off > 0; off >>= 1) {
#pragma unroll
        for (int e = 0; e < 8; e++) {
            aR[e] += __shfl_xor_sync(0xffffffffu, aR[e], off);
            aN[e] += __shfl_xor_sync(0xffffffffu, aN[e], off);
        }
    }

    if (lane == 0) {
        float logits[8], noisy[8];
#pragma unroll
        for (int e = 0; e < 8; e++) {
            logits[e] = aR[e] + br[e];
            float nl = aN[e] + bn[e];
            float sp = (nl > 20.f) ? nl : log1pf(expf(nl));
            noisy[e] = logits[e] + noise[(size_t)warp * E_NUM + e] * sp;
        }
        // top-2 (first occurrence wins ties, like jax top_k)
        int i1 = 0;
#pragma unroll
        for (int e = 1; e < 8; e++) if (noisy[e] > noisy[i1]) i1 = e;
        int i2 = -1;
#pragma unroll
        for (int e = 0; e < 8; e++) {
            if (e == i1) continue;
            if (i2 < 0 || noisy[e] > noisy[i2]) i2 = e;
        }
        float m = noisy[i1];
        float e1 = 1.0f;
        float e2 = expf(noisy[i2] - m);
        float s = e1 + e2;
        float g1 = e1 / s, g2 = e2 / s;

        // softmax_gating over plain logits
        float lm = logits[0];
#pragma unroll
        for (int e = 1; e < 8; e++) lm = fmaxf(lm, logits[e]);
        float se = 0.f, ex[8];
#pragma unroll
        for (int e = 0; e < 8; e++) { ex[e] = expf(logits[e] - lm); se += ex[e]; }
#pragma unroll
        for (int e = 0; e < 8; e++) gate_out[(size_t)warp * E_NUM + e] = ex[e] / se;

        int s1 = atomicAdd(&g_counts[i1], 1);
        g_list[i1 * CAP + s1] = warp;
        g_gate[i1 * CAP + s1] = g1;
        int s2 = atomicAdd(&g_counts[i2], 1);
        g_list[i2 * CAP + s2] = warp;
        g_gate[i2 * CAP + s2] = g2;
        g_pair[warp * 2 + 0] = i1 * CAP + s1;
        g_pair[warp * 2 + 1] = i2 * CAP + s2;
    }
}

// ---------------- Grouped GEMM tiles ----------------
#define BM 64
#define BN 64
#define BK 16
#define APAD 4

// GEMM1: h = relu(gather(x) @ W1[e] + b1[e]) -> g_hbuf
__global__ void gemm1_kernel(const float* __restrict__ x,
                             const float* __restrict__ W1,
                             const float* __restrict__ b1) {
    int e = blockIdx.z;
    int count = g_counts[e];
    int m0 = blockIdx.y * BM;
    if (m0 >= count) return;
    int n0 = blockIdx.x * BN;

    __shared__ float As[BK][BM + APAD];
    __shared__ float Bs[BK][BN];
    __shared__ int stok[BM];

    int tid = threadIdx.x;          // 256 threads
    int tx = tid & 15, ty = tid >> 4;

    if (tid < BM) {
        int row = m0 + tid;
        stok[tid] = (row < count) ? g_list[e * CAP + tid + m0] : -1;
    }
    __syncthreads();

    const float* Be = W1 + (size_t)e * D_DIM * H_DIM;
    float acc[4][4];
#pragma unroll
    for (int i = 0; i < 4; i++)
#pragma unroll
        for (int j = 0; j < 4; j++) acc[i][j] = 0.f;

    int a_m = tid >> 2, a_kq = tid & 3;      // A: 64 rows x 4 float4 in k
    int b_k = tid >> 4, b_nq = tid & 15;     // B: 16 rows x 16 float4 in n

    for (int kk = 0; kk < D_DIM; kk += BK) {
        // load A (gathered)
        int tok = stok[a_m];
        float4 av = make_float4(0.f, 0.f, 0.f, 0.f);
        if (tok >= 0) av = *(const float4*)(x + (size_t)tok * D_DIM + kk + a_kq * 4);
        As[a_kq * 4 + 0][a_m] = av.x;
        As[a_kq * 4 + 1][a_m] = av.y;
        As[a_kq * 4 + 2][a_m] = av.z;
        As[a_kq * 4 + 3][a_m] = av.w;
        // load B
        float4 bv = *(const float4*)(Be + (size_t)(kk + b_k) * H_DIM + n0 + b_nq * 4);
        *(float4*)&Bs[b_k][b_nq * 4] = bv;
        __syncthreads();

#pragma unroll
        for (int k = 0; k < BK; k++) {
            float4 a = *(float4*)&As[k][ty * 4];
            float4 b = *(float4*)&Bs[k][tx * 4];
            float ar[4] = {a.x, a.y, a.z, a.w};
            float bb[4] = {b.x, b.y, b.z, b.w};
#pragma unroll
            for (int i = 0; i < 4; i++)
#pragma unroll
                for (int j = 0; j < 4; j++) acc[i][j] += ar[i] * bb[j];
        }
        __syncthreads();
    }

#pragma unroll
    for (int i = 0; i < 4; i++) {
        int m = m0 + ty * 4 + i;
        if (m >= count) continue;
        size_t rowoff = ((size_t)e * CAP + m) * H_DIM;
#pragma unroll
        for (int j = 0; j < 4; j++) {
            int n = n0 + tx * 4 + j;
            float v = acc[i][j] + b1[e * H_DIM + n];
            g_hbuf[rowoff + n] = fmaxf(v, 0.f);
        }
    }
}

// GEMM2: y = gate * (h @ W2[e] + b2[e]) -> g_ybuf
__global__ void gemm2_kernel(const float* __restrict__ W2,
                             const float* __restrict__ b2) {
    int e = blockIdx.z;
    int count = g_counts[e];
    int m0 = blockIdx.y * BM;
    if (m0 >= count) return;
    int n0 = blockIdx.x * BN;

    __shared__ float As[BK][BM + APAD];
    __shared__ float Bs[BK][BN];

    int tid = threadIdx.x;
    int tx = tid & 15, ty = tid >> 4;

    const float* Be = W2 + (size_t)e * H_DIM * D_DIM;
    float acc[4][4];
#pragma unroll
    for (int i = 0; i < 4; i++)
#pragma unroll
        for (int j = 0; j < 4; j++) acc[i][j] = 0.f;

    int a_m = tid >> 2, a_kq = tid & 3;
    int b_k = tid >> 4, b_nq = tid & 15;
    size_t abase = ((size_t)e * CAP + m0) * H_DIM;

    for (int kk = 0; kk < H_DIM; kk += BK) {
        float4 av = make_float4(0.f, 0.f, 0.f, 0.f);
        if (m0 + a_m < count)
            av = *(const float4*)(g_hbuf + abase + (size_t)a_m * H_DIM + kk + a_kq * 4);
        As[a_kq * 4 + 0][a_m] = av.x;
        As[a_kq * 4 + 1][a_m] = av.y;
        As[a_kq * 4 + 2][a_m] = av.z;
        As[a_kq * 4 + 3][a_m] = av.w;
        float4 bv = *(const float4*)(Be + (size_t)(kk + b_k) * D_DIM + n0 + b_nq * 4);
        *(float4*)&Bs[b_k][b_nq * 4] = bv;
        __syncthreads();

#pragma unroll
        for (int k = 0; k < BK; k++) {
            float4 a = *(float4*)&As[k][ty * 4];
            float4 b = *(float4*)&Bs[k][tx * 4];
            float ar[4] = {a.x, a.y, a.z, a.w};
            float bb[4] = {b.x, b.y, b.z, b.w};
#pragma unroll
            for (int i = 0; i < 4; i++)
#pragma unroll
                for (int j = 0; j < 4; j++) acc[i][j] += ar[i] * bb[j];
        }
        __syncthreads();
    }

#pragma unroll
    for (int i = 0; i < 4; i++) {
        int m = m0 + ty * 4 + i;
        if (m >= count) continue;
        int pair = e * CAP + m;
        float g = g_gate[pair];
        size_t rowoff = (size_t)pair * D_DIM;
#pragma unroll
        for (int j = 0; j < 4; j++) {
            int n = n0 + tx * 4 + j;
            g_ybuf[rowoff + n] = g * (acc[i][j] + b2[e * D_DIM + n]);
        }
    }
}

// ---------------- Combine: out[t] = y[pair0] + y[pair1] ----------------
__global__ void combine_kernel(float* __restrict__ out) {
    int t = blockIdx.x;
    int i = threadIdx.x;   // 256 threads, one float4 each (D=1024)
    int p0 = g_pair[2 * t + 0];
    int p1 = g_pair[2 * t + 1];
    float4 a = ((const float4*)(g_ybuf + (size_t)p0 * D_DIM))[i];
    float4 b = ((const float4*)(g_ybuf + (size_t)p1 * D_DIM))[i];
    float4 r;
    r.x = a.x + b.x; r.y = a.y + b.y; r.z = a.z + b.z; r.w = a.w + b.w;
    ((float4*)(out + (size_t)t * D_DIM))[i] = r;
}

extern "C" void kernel_launch(void* const* d_in, const int* in_sizes, int n_in,
                              void* d_out, int out_size) {
    const float* x     = (const float*)d_in[0];
    const float* noise = (const float*)d_in[1];
    const float* Wr    = (const float*)d_in[2];
    const float* br    = (const float*)d_in[3];
    const float* Wn    = (const float*)d_in[4];
    const float* bn    = (const float*)d_in[5];
    const float* W1    = (const float*)d_in[6];
    const float* b1    = (const float*)d_in[7];
    const float* W2    = (const float*)d_in[8];
    const float* b2    = (const float*)d_in[9];
    float* out = (float*)d_out;

    float* final_out  = out;                               // [B,S,D]
    float* gating_out = out + (size_t)T_TOK * D_DIM;       // [B,S,E]

    zero_counts_kernel<<<1, 32>>>();

    // router: one warp per token -> 4096 warps -> 512 blocks of 256 threads
    router_kernel<<<512, 256>>>(x, noise, Wr, br, Wn, bn, gating_out);

    {
        dim3 grid(H_DIM / BN, CAP / BM, E_NUM);   // 64 x 64 x 8 (most tiles early-exit)
        gemm1_kernel<<<grid, 256>>>(x, W1, b1);
    }
    {
        dim3 grid(D_DIM / BN, CAP / BM, E_NUM);   // 16 x 64 x 8
        gemm2_kernel<<<grid, 256>>>(W2, b2);
    }
    combine_kernel<<<T_TOK, 256>>>(final_out);
}

// round 4
// speedup vs baseline: 3.1602x; 3.1602x over previous
#include <cuda_runtime.h>
#include <math.h>

#define T_TOK 4096   // B*S
#define D_DIM 1024
#define E_NUM 8
#define H_DIM 4096
#define CAP   4096   // worst-case tokens per expert

// ---- static scratch (allowed: __device__ globals) ----
__device__ float g_hbuf[(size_t)E_NUM * CAP * H_DIM];   // 512 MB
__device__ float g_ybuf[(size_t)E_NUM * CAP * D_DIM];   // 128 MB
__device__ int   g_counts[E_NUM];
__device__ int   g_list[E_NUM * CAP];
__device__ float g_gate[E_NUM * CAP];
__device__ int   g_pair[T_TOK * 2];

__global__ void zero_counts_kernel() {
    if (threadIdx.x < E_NUM) g_counts[threadIdx.x] = 0;
}

// ---------------- Router: one warp per token ----------------
__global__ void router_kernel(const float* __restrict__ x,
                              const float* __restrict__ noise,
                              const float* __restrict__ Wr, const float* __restrict__ br,
                              const float* __restrict__ Wn, const float* __restrict__ bn,
                              float* __restrict__ gate_out /* [T,E] */) {
    int warp = (blockIdx.x * blockDim.x + threadIdx.x) >> 5;
    int lane = threadIdx.x & 31;
    if (warp >= T_TOK) return;

    const float* xr = x + (size_t)warp * D_DIM;
    float aR[8], aN[8];
#pragma unroll
    for (int e = 0; e < 8; e++) { aR[e] = 0.f; aN[e] = 0.f; }

    for (int d0 = lane * 4; d0 < D_DIM; d0 += 32 * 4) {
        float4 xv = *(const float4*)(xr + d0);
        float xs[4] = {xv.x, xv.y, xv.z, xv.w};
#pragma unroll
        for (int u = 0; u < 4; ++u) {
            float xd = xs[u];
            const float4* wr = (const float4*)(Wr + (size_t)(d0 + u) * E_NUM);
            float4 r0 = wr[0], r1 = wr[1];
            const float4* wn = (const float4*)(Wn + (size_t)(d0 + u) * E_NUM);
            float4 q0 = wn[0], q1 = wn[1];
            aR[0] += xd * r0.x; aR[1] += xd * r0.y; aR[2] += xd * r0.z; aR[3] += xd * r0.w;
            aR[4] += xd * r1.x; aR[5] += xd * r1.y; aR[6] += xd * r1.z; aR[7] += xd * r1.w;
            aN[0] += xd * q0.x; aN[1] += xd * q0.y; aN[2] += xd * q0.z; aN[3] += xd * q0.w;
            aN[4] += xd * q1.x; aN[5] += xd * q1.y; aN[6] += xd * q1.z; aN[7] += xd * q1.w;
        }
    }
#pragma unroll
    for (int off = 16; off > 0; off >>= 1) {
#pragma unroll
        for (int e = 0; e < 8; e++) {
            aR[e] += __shfl_xor_sync(0xffffffffu, aR[e], off);
            aN[e] += __shfl_xor_sync(0xffffffffu, aN[e], off);
        }
    }

    if (lane == 0) {
        float logits[8], noisy[8];
#pragma unroll
        for (int e = 0; e < 8; e++) {
            logits[e] = aR[e] + br[e];
            float nl = aN[e] + bn[e];
            float sp = (nl > 20.f) ? nl : log1pf(expf(nl));
            noisy[e] = logits[e] + noise[(size_t)warp * E_NUM + e] * sp;
        }
        int i1 = 0;
#pragma unroll
        for (int e = 1; e < 8; e++) if (noisy[e] > noisy[i1]) i1 = e;
        int i2 = -1;
#pragma unroll
        for (int e = 0; e < 8; e++) {
            if (e == i1) continue;
            if (i2 < 0 || noisy[e] > noisy[i2]) i2 = e;
        }
        float m = noisy[i1];
        float e2 = expf(noisy[i2] - m);
        float s = 1.0f + e2;
        float g1 = 1.0f / s, g2 = e2 / s;

        float lm = logits[0];
#pragma unroll
        for (int e = 1; e < 8; e++) lm = fmaxf(lm, logits[e]);
        float se = 0.f, ex[8];
#pragma unroll
        for (int e = 0; e < 8; e++) { ex[e] = expf(logits[e] - lm); se += ex[e]; }
#pragma unroll
        for (int e = 0; e < 8; e++) gate_out[(size_t)warp * E_NUM + e] = ex[e] / se;

        int s1 = atomicAdd(&g_counts[i1], 1);
        g_list[i1 * CAP + s1] = warp;
        g_gate[i1 * CAP + s1] = g1;
        int s2 = atomicAdd(&g_counts[i2], 1);
        g_list[i2 * CAP + s2] = warp;
        g_gate[i2 * CAP + s2] = g2;
        g_pair[warp * 2 + 0] = i1 * CAP + s1;
        g_pair[warp * 2 + 1] = i2 * CAP + s2;
    }
}

// ---------------- TF32 tensor-core grouped GEMM ----------------
__device__ __forceinline__ unsigned cvt_tf32(float f) {
    unsigned o;
    asm volatile("cvt.rna.tf32.f32 %0, %1;\n" : "=r"(o) : "f"(f));
    return o;
}
__device__ __forceinline__ void cp16(unsigned dst, const float* src, bool p) {
    int sz = p ? 16 : 0;
    asm volatile("cp.async.cg.shared.global [%0], [%1], 16, %2;\n"
                 :: "r"(dst), "l"(src), "r"(sz));
}
__device__ __forceinline__ void mma8(float* c, const unsigned* a, const unsigned* b) {
    asm volatile(
        "mma.sync.aligned.m16n8k8.row.col.f32.tf32.tf32.f32 "
        "{%0,%1,%2,%3}, {%4,%5,%6,%7}, {%8,%9}, {%0,%1,%2,%3};\n"
        : "+f"(c[0]), "+f"(c[1]), "+f"(c[2]), "+f"(c[3])
        : "r"(a[0]), "r"(a[1]), "r"(a[2]), "r"(a[3]), "r"(b[0]), "r"(b[1]));
}

// G1: h = relu(gather(x) @ W1[e] + b1[e])    [K=1024, N=4096]
// !G1: y = gate * (h @ W2[e] + b2[e])        [K=4096, N=1024]
template<bool G1>
__global__ __launch_bounds__(256, 2)
void moe_gemm(const float* __restrict__ x,
              const float* __restrict__ W,
              const float* __restrict__ bias)
{
    constexpr int K = G1 ? D_DIM : H_DIM;
    constexpr int N = G1 ? H_DIM : D_DIM;

    int e = blockIdx.z;
    int count = g_counts[e];
    int m0 = blockIdx.y * 128;
    if (m0 >= count) return;
    int n0 = blockIdx.x * 128;

    __shared__ float As[2][128][20];
    __shared__ float Bs[2][16][136];
    __shared__ int stok[128];

    int tid = threadIdx.x;
    int wid = tid >> 5, lane = tid & 31;
    int gid = lane >> 2, tig = lane & 3;
    int warp_m = (wid & 1) * 64;
    int warp_n = (wid >> 1) * 32;

    if (G1) {
        if (tid < 128) {
            int r = m0 + tid;
            stok[tid] = (r < count) ? g_list[e * CAP + r] : -1;
        }
        __syncthreads();
    }

    // per-thread global->shared coords
    int a_m  = tid >> 2;           // 0..63 (and +64)
    int a_kq = (tid & 3) * 4;      // 0,4,8,12
    int b_r  = tid >> 4;           // 0..15
    int b_c  = (tid & 15) * 4;     // 0..60 (and +64)

    const float* We = W + (size_t)e * K * N;
    const float* biasrow = bias + (size_t)e * N;

    const float *arow0, *arow1;
    bool ap0, ap1;
    if (G1) {
        int t0 = stok[a_m], t1 = stok[a_m + 64];
        ap0 = t0 >= 0; ap1 = t1 >= 0;
        arow0 = x + (size_t)(ap0 ? t0 : 0) * D_DIM;
        arow1 = x + (size_t)(ap1 ? t1 : 0) * D_DIM;
    } else {
        ap0 = (m0 + a_m) < count;
        ap1 = (m0 + a_m + 64) < count;
        arow0 = g_hbuf + ((size_t)e * CAP + (ap0 ? m0 + a_m : 0)) * (size_t)H_DIM;
        arow1 = g_hbuf + ((size_t)e * CAP + (ap1 ? m0 + a_m + 64 : 0)) * (size_t)H_DIM;
    }

    unsigned sA0[2], sA1[2], sB0[2], sB1[2];
#pragma unroll
    for (int b = 0; b < 2; b++) {
        sA0[b] = (unsigned)__cvta_generic_to_shared(&As[b][a_m][a_kq]);
        sA1[b] = (unsigned)__cvta_generic_to_shared(&As[b][a_m + 64][a_kq]);
        sB0[b] = (unsigned)__cvta_generic_to_shared(&Bs[b][b_r][b_c]);
        sB1[b] = (unsigned)__cvta_generic_to_shared(&Bs[b][b_r][b_c + 64]);
    }

    float acc[4][4][4];
#pragma unroll
    for (int i = 0; i < 4; i++)
#pragma unroll
        for (int j = 0; j < 4; j++)
#pragma unroll
            for (int r = 0; r < 4; r++) acc[i][j][r] = 0.f;

    const int nK = K / 16;

    // prologue: tile 0 -> buf 0
    {
        cp16(sA0[0], arow0 + a_kq, ap0);
        cp16(sA1[0], arow1 + a_kq, ap1);
        cp16(sB0[0], We + (size_t)b_r * N + n0 + b_c, true);
        cp16(sB1[0], We + (size_t)b_r * N + n0 + b_c + 64, true);
        asm volatile("cp.async.commit_group;\n");
        asm volatile("cp.async.wait_group 0;\n");
        __syncthreads();
    }

    int buf = 0;
    for (int t = 0; t < nK; ++t) {
        if (t + 1 < nK) {
            int kk = (t + 1) * 16;
            cp16(sA0[buf ^ 1], arow0 + kk + a_kq, ap0);
            cp16(sA1[buf ^ 1], arow1 + kk + a_kq, ap1);
            cp16(sB0[buf ^ 1], We + (size_t)(kk + b_r) * N + n0 + b_c, true);
            cp16(sB1[buf ^ 1], We + (size_t)(kk + b_r) * N + n0 + b_c + 64, true);
            asm volatile("cp.async.commit_group;\n");
        }

#pragma unroll
        for (int ks = 0; ks < 16; ks += 8) {
            unsigned af[4][4], bf[4][2];
#pragma unroll
            for (int mt = 0; mt < 4; mt++) {
                int m = warp_m + mt * 16 + gid;
                af[mt][0] = cvt_tf32(As[buf][m][ks + tig]);
                af[mt][1] = cvt_tf32(As[buf][m + 8][ks + tig]);
                af[mt][2] = cvt_tf32(As[buf][m][ks + tig + 4]);
                af[mt][3] = cvt_tf32(As[buf][m + 8][ks + tig + 4]);
            }
#pragma unroll
            for (int nt = 0; nt < 4; nt++) {
                int n = warp_n + nt * 8 + gid;
                bf[nt][0] = cvt_tf32(Bs[buf][ks + tig][n]);
                bf[nt][1] = cvt_tf32(Bs[buf][ks + tig + 4][n]);
            }
#pragma unroll
            for (int mt = 0; mt < 4; mt++)
#pragma unroll
                for (int nt = 0; nt < 4; nt++)
                    mma8(acc[mt][nt], af[mt], bf[nt]);
        }

        if (t + 1 < nK) asm volatile("cp.async.wait_group 0;\n");
        __syncthreads();
        buf ^= 1;
    }

    // ---------------- epilogue ----------------
    float* outbuf = G1 ? g_hbuf : g_ybuf;
#pragma unroll
    for (int mt = 0; mt < 4; mt++) {
        int mg0 = m0 + warp_m + mt * 16 + gid;
        int mg1 = mg0 + 8;
#pragma unroll
        for (int half = 0; half < 2; half++) {
            int mg = half ? mg1 : mg0;
            if (mg >= count) continue;
            size_t rowoff = ((size_t)e * CAP + mg) * (size_t)N;
            float gate = 1.0f;
            if (!G1) gate = g_gate[e * CAP + mg];
#pragma unroll
            for (int nt = 0; nt < 4; nt++) {
                int n = n0 + warp_n + nt * 8 + tig * 2;
                float v0 = acc[mt][nt][half * 2 + 0] + biasrow[n];
                float v1 = acc[mt][nt][half * 2 + 1] + biasrow[n + 1];
                if (G1) {
                    v0 = fmaxf(v0, 0.f);
                    v1 = fmaxf(v1, 0.f);
                } else {
                    v0 *= gate;
                    v1 *= gate;
                }
                *(float2*)(outbuf + rowoff + n) = make_float2(v0, v1);
            }
        }
    }
}

// ---------------- Combine: out[t] = y[pair0] + y[pair1] ----------------
__global__ void combine_kernel(float* __restrict__ out) {
    int t = blockIdx.x;
    int i = threadIdx.x;   // 256 threads, one float4 each (D=1024)
    int p0 = g_pair[2 * t + 0];
    int p1 = g_pair[2 * t + 1];
    float4 a = ((const float4*)(g_ybuf + (size_t)p0 * D_DIM))[i];
    float4 b = ((const float4*)(g_ybuf + (size_t)p1 * D_DIM))[i];
    float4 r;
    r.x = a.x + b.x; r.y = a.y + b.y; r.z = a.z + b.z; r.w = a.w + b.w;
    ((float4*)(out + (size_t)t * D_DIM))[i] = r;
}

extern "C" void kernel_launch(void* const* d_in, const int* in_sizes, int n_in,
                              void* d_out, int out_size) {
    const float* x     = (const float*)d_in[0];
    const float* noise = (const float*)d_in[1];
    const float* Wr    = (const float*)d_in[2];
    const float* br    = (const float*)d_in[3];
    const float* Wn    = (const float*)d_in[4];
    const float* bn    = (const float*)d_in[5];
    const float* W1    = (const float*)d_in[6];
    const float* b1    = (const float*)d_in[7];
    const float* W2    = (const float*)d_in[8];
    const float* b2    = (const float*)d_in[9];
    float* out = (float*)d_out;

    float* final_out  = out;                               // [B,S,D]
    float* gating_out = out + (size_t)T_TOK * D_DIM;       // [B,S,E]

    zero_counts_kernel<<<1, 32>>>();
    router_kernel<<<512, 256>>>(x, noise, Wr, br, Wn, bn, gating_out);

    {
        dim3 grid(H_DIM / 128, CAP / 128, E_NUM);   // 32 x 32 x 8 (most tiles early-exit)
        moe_gemm<true><<<grid, 256>>>(x, W1, b1);
    }
    {
        dim3 grid(D_DIM / 128, CAP / 128, E_NUM);   // 8 x 32 x 8
        moe_gemm<false><<<grid, 256>>>(nullptr, W2, b2);
    }
    combine_kernel<<<T_TOK, 256>>>(final_out);
}